// round 1
// baseline (speedup 1.0000x reference)
#include <cuda_runtime.h>

#define N_USERS 100000
#define N_ITEMS 50000
#define NTOT    150000
#define D       64
#define NNZ     2000000
#define BATCH   16384

// Scratch feature buffers (allocation-free: __device__ globals)
__device__ float d_buf0[NTOT * D];
__device__ float d_buf1[NTOT * D];
__device__ float d_acc [NTOT * D];

// ---------------------------------------------------------------------------
// init: buf0 = concat(emb_user, emb_item); acc = buf0; buf1 = 0
// ---------------------------------------------------------------------------
__global__ void init_kernel(const float* __restrict__ eu,
                            const float* __restrict__ ei) {
    int i = blockIdx.x * blockDim.x + threadIdx.x;   // float4 index
    const int total4 = NTOT * D / 4;
    if (i >= total4) return;
    const int uhalf = N_USERS * D / 4;
    float4 v;
    if (i < uhalf) v = ((const float4*)eu)[i];
    else           v = ((const float4*)ei)[i - uhalf];
    ((float4*)d_buf0)[i] = v;
    ((float4*)d_acc )[i] = v;
    ((float4*)d_buf1)[i] = make_float4(0.f, 0.f, 0.f, 0.f);
}

// ---------------------------------------------------------------------------
// SpMM (COO, scatter): xout[row] += val * xin[col]
// 16 threads per edge, one float4 per thread. Vector red.global (no return).
// ---------------------------------------------------------------------------
__global__ void spmm_kernel(const float* __restrict__ xin,
                            float*       __restrict__ xout,
                            const float* __restrict__ gval,
                            const int*   __restrict__ grow,
                            const int*   __restrict__ gcol) {
    int gid = blockIdx.x * blockDim.x + threadIdx.x;   // NNZ*16 = 32M < 2^31
    int e = gid >> 4;
    int t = gid & 15;
    if (e >= NNZ) return;
    int   c = gcol[e];
    int   r = grow[e];
    float v = gval[e];
    float4 x = ((const float4*)xin)[c * 16 + t];
    float4* dst = (float4*)xout + r * 16 + t;
    asm volatile("red.global.add.v4.f32 [%0], {%1, %2, %3, %4};"
                 :: "l"(dst), "f"(v * x.x), "f"(v * x.y),
                    "f"(v * x.z), "f"(v * x.w)
                 : "memory");
}

// ---------------------------------------------------------------------------
// acc += src ; zbuf = 0   (prepares zbuf as the next SpMM output)
// ---------------------------------------------------------------------------
__global__ void add_zero_kernel(const float* __restrict__ src,
                                float*       __restrict__ zbuf) {
    int i = blockIdx.x * blockDim.x + threadIdx.x;
    const int total4 = NTOT * D / 4;
    if (i >= total4) return;
    float4 a = ((const float4*)d_acc)[i];
    float4 s = ((const float4*)src)[i];
    a.x += s.x; a.y += s.y; a.z += s.z; a.w += s.w;
    ((float4*)d_acc)[i] = a;
    ((float4*)zbuf)[i] = make_float4(0.f, 0.f, 0.f, 0.f);
}

// ---------------------------------------------------------------------------
// Tail: per-batch-element gather + 2 matvecs + softmax/sigmoid + dot.
// One warp per element; weights in shared memory padded to stride 65.
// light = (acc + lastbuf) / 4  (last SpMM output not yet folded into acc)
// ---------------------------------------------------------------------------
__global__ void final_kernel(const float* __restrict__ lastbuf,
                             const float* __restrict__ w_user,
                             const float* __restrict__ w_item,
                             const float* __restrict__ xe1,
                             const float* __restrict__ xe0,
                             const int*   __restrict__ users,
                             const int*   __restrict__ items,
                             const int*   __restrict__ xij,
                             float*       __restrict__ out) {
    __shared__ float wu[64 * 65];
    __shared__ float wi[64 * 65];
    int tid = threadIdx.x;                     // 128 threads
    for (int idx = tid; idx < 64 * 64; idx += blockDim.x) {
        int r = idx >> 6, c = idx & 63;
        wu[r * 65 + c] = w_user[idx];
        wi[r * 65 + c] = w_item[idx];
    }
    __syncthreads();

    int warp = tid >> 5;
    int lane = tid & 31;

    // 512 blocks * 4 warps * 8 elems = 16384
    int b_base = blockIdx.x * 32 + warp * 8;
    for (int bi = 0; bi < 8; bi++) {
        int b = b_base + bi;
        int u  = users[b];
        int it = items[b];
        int ir = N_USERS + it;

        float ue0 = (d_acc[u * 64 + lane]       + lastbuf[u * 64 + lane])       * 0.25f;
        float ue1 = (d_acc[u * 64 + 32 + lane]  + lastbuf[u * 64 + 32 + lane])  * 0.25f;
        float ie0 = (d_acc[ir * 64 + lane]      + lastbuf[ir * 64 + lane])      * 0.25f;
        float ie1 = (d_acc[ir * 64 + 32 + lane] + lastbuf[ir * 64 + 32 + lane]) * 0.25f;

        // matvecs: out[j] = sum_k v[k] * W[j*64+k], j = lane and lane+32
        float uo0 = 0.f, uo1 = 0.f, io0 = 0.f, io1 = 0.f;
        #pragma unroll
        for (int k = 0; k < 32; k++) {
            float au = __shfl_sync(0xffffffffu, ue0, k);
            float ai = __shfl_sync(0xffffffffu, ie0, k);
            uo0 += au * wu[lane * 65 + k];
            uo1 += au * wu[(lane + 32) * 65 + k];
            io0 += ai * wi[lane * 65 + k];
            io1 += ai * wi[(lane + 32) * 65 + k];
        }
        #pragma unroll
        for (int k = 0; k < 32; k++) {
            float au = __shfl_sync(0xffffffffu, ue1, k);
            float ai = __shfl_sync(0xffffffffu, ie1, k);
            uo0 += au * wu[lane * 65 + 32 + k];
            uo1 += au * wu[(lane + 32) * 65 + 32 + k];
            io0 += ai * wi[lane * 65 + 32 + k];
            io1 += ai * wi[(lane + 32) * 65 + 32 + k];
        }

        // softmax over the 64 uo values (warp-wide)
        float m = fmaxf(uo0, uo1);
        #pragma unroll
        for (int o = 16; o; o >>= 1)
            m = fmaxf(m, __shfl_xor_sync(0xffffffffu, m, o));
        float eu0 = expf(uo0 - m);
        float eu1 = expf(uo1 - m);
        float s = eu0 + eu1;
        #pragma unroll
        for (int o = 16; o; o >>= 1)
            s += __shfl_xor_sync(0xffffffffu, s, o);
        float scale = 0.5f / s;                 // (1 - hx) * softmax

        // sigmoid of item projections
        float sg0 = 1.f / (1.f + expf(-io0));
        float sg1 = 1.f / (1.f + expf(-io1));

        float part = scale * (eu0 * sg0 + eu1 * sg1);
        #pragma unroll
        for (int o = 16; o; o >>= 1)
            part += __shfl_xor_sync(0xffffffffu, part, o);

        if (lane == 0) {
            float xe  = (xij[b] > 0) ? xe1[it] : xe0[it];
            float sgx = 1.f / (1.f + expf(-xe));
            out[b] = part + 0.5f * sgx;
        }
    }
}

// ---------------------------------------------------------------------------
extern "C" void kernel_launch(void* const* d_in, const int* in_sizes, int n_in,
                              void* d_out, int out_size) {
    (void)in_sizes; (void)n_in; (void)out_size;
    const float* emb_user = (const float*)d_in[0];
    const float* emb_item = (const float*)d_in[1];
    const float* w_user   = (const float*)d_in[2];
    const float* w_item   = (const float*)d_in[3];
    const float* xe1      = (const float*)d_in[4];
    const float* xe0      = (const float*)d_in[5];
    const float* g_val    = (const float*)d_in[6];
    const int*   g_row    = (const int*)d_in[7];
    const int*   g_col    = (const int*)d_in[8];
    const int*   users    = (const int*)d_in[9];
    const int*   items    = (const int*)d_in[10];
    const int*   xij      = (const int*)d_in[11];
    float* out = (float*)d_out;

    float *p_buf0, *p_buf1;
    cudaGetSymbolAddress((void**)&p_buf0, d_buf0);
    cudaGetSymbolAddress((void**)&p_buf1, d_buf1);

    const int total4 = NTOT * D / 4;
    const int eltBlocks = (total4 + 255) / 256;
    const int spmmBlocks = (NNZ * 16 + 255) / 256;

    // init: buf0 = e, acc = e, buf1 = 0
    init_kernel<<<eltBlocks, 256>>>(emb_user, emb_item);
    // layer 1: buf0 -> buf1
    spmm_kernel<<<spmmBlocks, 256>>>(p_buf0, p_buf1, g_val, g_row, g_col);
    add_zero_kernel<<<eltBlocks, 256>>>(p_buf1, p_buf0);   // acc += buf1; buf0 = 0
    // layer 2: buf1 -> buf0
    spmm_kernel<<<spmmBlocks, 256>>>(p_buf1, p_buf0, g_val, g_row, g_col);
    add_zero_kernel<<<eltBlocks, 256>>>(p_buf0, p_buf1);   // acc += buf0; buf1 = 0
    // layer 3: buf0 -> buf1 (folded into final read as acc + buf1)
    spmm_kernel<<<spmmBlocks, 256>>>(p_buf0, p_buf1, g_val, g_row, g_col);

    final_kernel<<<BATCH / 32, 128>>>(p_buf1, w_user, w_item, xe1, xe0,
                                      users, items, xij, out);
}

// round 2
// speedup vs baseline: 1.9168x; 1.9168x over previous
#include <cuda_runtime.h>

#define N_USERS 100000
#define N_ITEMS 50000
#define NTOT    150000
#define D       64
#define NNZ     2000000
#define BATCH   16384
#define SCAN_BLOCKS 586   // ceil(NTOT/256)

// Scratch (allocation-free: __device__ globals)
__device__ float  d_buf1[NTOT * D];
__device__ float  d_buf2[NTOT * D];
__device__ float  d_buf3[NTOT * D];
__device__ int    d_cnt [NTOT];
__device__ int    d_cur [NTOT];
__device__ int    d_rs  [NTOT + 1];
__device__ int    d_bsum[SCAN_BLOCKS];
__device__ int    d_boff[SCAN_BLOCKS];
__device__ float2 d_scv [NNZ];          // packed (col_as_float_bits, val)

// ---------------------------------------------------------------------------
// zero counters
// ---------------------------------------------------------------------------
__global__ void zero_kernel() {
    int i = blockIdx.x * blockDim.x + threadIdx.x;
    if (i < NTOT) { d_cnt[i] = 0; d_cur[i] = 0; }
}

// ---------------------------------------------------------------------------
// histogram of rows
// ---------------------------------------------------------------------------
__global__ void hist_kernel(const int* __restrict__ grow) {
    int e = blockIdx.x * blockDim.x + threadIdx.x;
    if (e < NNZ) atomicAdd(&d_cnt[grow[e]], 1);
}

// ---------------------------------------------------------------------------
// scan stage 1: per-block exclusive scan of d_cnt -> d_rs, block sums -> d_bsum
// ---------------------------------------------------------------------------
__global__ void scan1_kernel() {
    __shared__ int ws[8];
    int i = blockIdx.x * 256 + threadIdx.x;
    int lane = threadIdx.x & 31, w = threadIdx.x >> 5;
    int c = (i < NTOT) ? d_cnt[i] : 0;
    int x = c;
    #pragma unroll
    for (int o = 1; o < 32; o <<= 1) {
        int y = __shfl_up_sync(0xffffffffu, x, o);
        if (lane >= o) x += y;
    }
    if (lane == 31) ws[w] = x;
    __syncthreads();
    if (w == 0 && lane < 8) {
        int s = ws[lane];
        #pragma unroll
        for (int o = 1; o < 8; o <<= 1) {
            int y = __shfl_up_sync(0xffu, s, o);
            if (lane >= o) s += y;
        }
        ws[lane] = s;
    }
    __syncthreads();
    int off = (w > 0) ? ws[w - 1] : 0;
    int incl = x + off;
    if (i < NTOT) d_rs[i] = incl - c;
    if (threadIdx.x == 255) d_bsum[blockIdx.x] = incl;
}

// ---------------------------------------------------------------------------
// scan stage 2: one warp scans the block sums -> d_boff (exclusive)
// ---------------------------------------------------------------------------
__global__ void scan2_kernel() {
    int lane = threadIdx.x;   // 32 threads
    int carry = 0;
    for (int base = 0; base < SCAN_BLOCKS; base += 32) {
        int idx = base + lane;
        int v = (idx < SCAN_BLOCKS) ? d_bsum[idx] : 0;
        int x = v;
        #pragma unroll
        for (int o = 1; o < 32; o <<= 1) {
            int y = __shfl_up_sync(0xffffffffu, x, o);
            if (lane >= o) x += y;
        }
        if (idx < SCAN_BLOCKS) d_boff[idx] = carry + x - v;
        carry += __shfl_sync(0xffffffffu, x, 31);
    }
    if (lane == 0) d_rs[NTOT] = carry;   // == NNZ
}

// ---------------------------------------------------------------------------
// scan stage 3: add block offsets
// ---------------------------------------------------------------------------
__global__ void scan3_kernel() {
    int i = blockIdx.x * 256 + threadIdx.x;
    if (i < NTOT) d_rs[i] += d_boff[blockIdx.x];
}

// ---------------------------------------------------------------------------
// permute edges into CSR order, packing (col, val) into float2
// ---------------------------------------------------------------------------
__global__ void permute_kernel(const int* __restrict__ grow,
                               const int* __restrict__ gcol,
                               const float* __restrict__ gval) {
    int e = blockIdx.x * blockDim.x + threadIdx.x;
    if (e >= NNZ) return;
    int r = grow[e];
    int pos = d_rs[r] + atomicAdd(&d_cur[r], 1);
    d_scv[pos] = make_float2(__int_as_float(gcol[e]), gval[e]);
}

// ---------------------------------------------------------------------------
// Gather SpMM: one row per 16 lanes, one float4 per lane, edge loop x4 unroll.
// Source is addressed via (user ptr, item ptr) pair so layer 1 can read the
// embeddings directly (xi == xu + N_USERS*16 for internal buffers).
// ---------------------------------------------------------------------------
__device__ __forceinline__ const float4* src_ptr(const float4* xu,
                                                 const float4* xi, int c) {
    return (c < N_USERS) ? (xu + (size_t)c * 16)
                         : (xi + (size_t)(c - N_USERS) * 16);
}

__global__ void spmm_gather_kernel(const float4* __restrict__ xu,
                                   const float4* __restrict__ xi,
                                   float4*       __restrict__ xout) {
    int gid = blockIdx.x * blockDim.x + threadIdx.x;
    int row = gid >> 4;
    int t   = gid & 15;
    if (row >= NTOT) return;
    int s = d_rs[row], e = d_rs[row + 1];
    float4 a = make_float4(0.f, 0.f, 0.f, 0.f);
    int i = s;
    for (; i + 4 <= e; i += 4) {
        float2 p0 = d_scv[i],     p1 = d_scv[i + 1];
        float2 p2 = d_scv[i + 2], p3 = d_scv[i + 3];
        float4 x0 = src_ptr(xu, xi, __float_as_int(p0.x))[t];
        float4 x1 = src_ptr(xu, xi, __float_as_int(p1.x))[t];
        float4 x2 = src_ptr(xu, xi, __float_as_int(p2.x))[t];
        float4 x3 = src_ptr(xu, xi, __float_as_int(p3.x))[t];
        a.x += p0.y * x0.x; a.y += p0.y * x0.y; a.z += p0.y * x0.z; a.w += p0.y * x0.w;
        a.x += p1.y * x1.x; a.y += p1.y * x1.y; a.z += p1.y * x1.z; a.w += p1.y * x1.w;
        a.x += p2.y * x2.x; a.y += p2.y * x2.y; a.z += p2.y * x2.z; a.w += p2.y * x2.w;
        a.x += p3.y * x3.x; a.y += p3.y * x3.y; a.z += p3.y * x3.z; a.w += p3.y * x3.w;
    }
    for (; i < e; i++) {
        float2 p = d_scv[i];
        float4 x = src_ptr(xu, xi, __float_as_int(p.x))[t];
        a.x += p.y * x.x; a.y += p.y * x.y; a.z += p.y * x.z; a.w += p.y * x.w;
    }
    xout[(size_t)row * 16 + t] = a;
}

// ---------------------------------------------------------------------------
// Tail: light[row] = (emb[row] + b1 + b2 + b3) / 4 at gathered rows,
// two 64x64 matvecs, softmax/sigmoid, dot. One warp per batch element.
// ---------------------------------------------------------------------------
__global__ void final_kernel(const float* __restrict__ eu,
                             const float* __restrict__ ei,
                             const float* __restrict__ w_user,
                             const float* __restrict__ w_item,
                             const float* __restrict__ xe1,
                             const float* __restrict__ xe0,
                             const int*   __restrict__ users,
                             const int*   __restrict__ items,
                             const int*   __restrict__ xij,
                             float*       __restrict__ out) {
    __shared__ float wu[64 * 65];
    __shared__ float wi[64 * 65];
    int tid = threadIdx.x;                     // 128 threads
    for (int idx = tid; idx < 64 * 64; idx += blockDim.x) {
        int r = idx >> 6, c = idx & 63;
        wu[r * 65 + c] = w_user[idx];
        wi[r * 65 + c] = w_item[idx];
    }
    __syncthreads();

    int warp = tid >> 5;
    int lane = tid & 31;

    int b_base = blockIdx.x * 32 + warp * 8;   // 512 blocks * 4 warps * 8
    for (int bi = 0; bi < 8; bi++) {
        int b = b_base + bi;
        int u  = users[b];
        int it = items[b];
        size_t uo = (size_t)u * 64;
        size_t io = (size_t)(N_USERS + it) * 64;
        size_t ie_off = (size_t)it * 64;

        float ue0 = (eu[uo + lane] + d_buf1[uo + lane] +
                     d_buf2[uo + lane] + d_buf3[uo + lane]) * 0.25f;
        float ue1 = (eu[uo + 32 + lane] + d_buf1[uo + 32 + lane] +
                     d_buf2[uo + 32 + lane] + d_buf3[uo + 32 + lane]) * 0.25f;
        float ie0 = (ei[ie_off + lane] + d_buf1[io + lane] +
                     d_buf2[io + lane] + d_buf3[io + lane]) * 0.25f;
        float ie1 = (ei[ie_off + 32 + lane] + d_buf1[io + 32 + lane] +
                     d_buf2[io + 32 + lane] + d_buf3[io + 32 + lane]) * 0.25f;

        float po0 = 0.f, po1 = 0.f, qo0 = 0.f, qo1 = 0.f;
        #pragma unroll
        for (int k = 0; k < 32; k++) {
            float au = __shfl_sync(0xffffffffu, ue0, k);
            float ai = __shfl_sync(0xffffffffu, ie0, k);
            po0 += au * wu[lane * 65 + k];
            po1 += au * wu[(lane + 32) * 65 + k];
            qo0 += ai * wi[lane * 65 + k];
            qo1 += ai * wi[(lane + 32) * 65 + k];
        }
        #pragma unroll
        for (int k = 0; k < 32; k++) {
            float au = __shfl_sync(0xffffffffu, ue1, k);
            float ai = __shfl_sync(0xffffffffu, ie1, k);
            po0 += au * wu[lane * 65 + 32 + k];
            po1 += au * wu[(lane + 32) * 65 + 32 + k];
            qo0 += ai * wi[lane * 65 + 32 + k];
            qo1 += ai * wi[(lane + 32) * 65 + 32 + k];
        }

        float m = fmaxf(po0, po1);
        #pragma unroll
        for (int o = 16; o; o >>= 1)
            m = fmaxf(m, __shfl_xor_sync(0xffffffffu, m, o));
        float e0 = expf(po0 - m);
        float e1 = expf(po1 - m);
        float s = e0 + e1;
        #pragma unroll
        for (int o = 16; o; o >>= 1)
            s += __shfl_xor_sync(0xffffffffu, s, o);
        float scale = 0.5f / s;                 // (1 - hx) * softmax

        float sg0 = 1.f / (1.f + expf(-qo0));
        float sg1 = 1.f / (1.f + expf(-qo1));

        float part = scale * (e0 * sg0 + e1 * sg1);
        #pragma unroll
        for (int o = 16; o; o >>= 1)
            part += __shfl_xor_sync(0xffffffffu, part, o);

        if (lane == 0) {
            float xe  = (xij[b] > 0) ? xe1[it] : xe0[it];
            float sgx = 1.f / (1.f + expf(-xe));
            out[b] = part + 0.5f * sgx;
        }
    }
}

// ---------------------------------------------------------------------------
extern "C" void kernel_launch(void* const* d_in, const int* in_sizes, int n_in,
                              void* d_out, int out_size) {
    (void)in_sizes; (void)n_in; (void)out_size;
    const float* emb_user = (const float*)d_in[0];
    const float* emb_item = (const float*)d_in[1];
    const float* w_user   = (const float*)d_in[2];
    const float* w_item   = (const float*)d_in[3];
    const float* xe1      = (const float*)d_in[4];
    const float* xe0      = (const float*)d_in[5];
    const float* g_val    = (const float*)d_in[6];
    const int*   g_row    = (const int*)d_in[7];
    const int*   g_col    = (const int*)d_in[8];
    const int*   users    = (const int*)d_in[9];
    const int*   items    = (const int*)d_in[10];
    const int*   xij      = (const int*)d_in[11];
    float* out = (float*)d_out;

    float *p_buf1, *p_buf2, *p_buf3;
    cudaGetSymbolAddress((void**)&p_buf1, d_buf1);
    cudaGetSymbolAddress((void**)&p_buf2, d_buf2);
    cudaGetSymbolAddress((void**)&p_buf3, d_buf3);

    const int nnzBlocks    = (NNZ + 255) / 256;
    const int gatherBlocks = (NTOT * 16 + 255) / 256;

    // CSR build
    zero_kernel<<<SCAN_BLOCKS, 256>>>();
    hist_kernel<<<nnzBlocks, 256>>>(g_row);
    scan1_kernel<<<SCAN_BLOCKS, 256>>>();
    scan2_kernel<<<1, 32>>>();
    scan3_kernel<<<SCAN_BLOCKS, 256>>>();
    permute_kernel<<<nnzBlocks, 256>>>(g_row, g_col, g_val);

    // 3 propagation layers (gather, no atomics, no zeroing)
    spmm_gather_kernel<<<gatherBlocks, 256>>>(
        (const float4*)emb_user, (const float4*)emb_item, (float4*)p_buf1);
    spmm_gather_kernel<<<gatherBlocks, 256>>>(
        (const float4*)p_buf1, (const float4*)p_buf1 + (size_t)N_USERS * 16,
        (float4*)p_buf2);
    spmm_gather_kernel<<<gatherBlocks, 256>>>(
        (const float4*)p_buf2, (const float4*)p_buf2 + (size_t)N_USERS * 16,
        (float4*)p_buf3);

    final_kernel<<<BATCH / 32, 128>>>(emb_user, emb_item, w_user, w_item,
                                      xe1, xe0, users, items, xij, out);
}

// round 4
// speedup vs baseline: 1.9638x; 1.0245x over previous
#include <cuda_runtime.h>

#define N_USERS 100000
#define N_ITEMS 50000
#define NTOT    150000
#define D       64
#define NNZ     2000000
#define BATCH   16384
#define SCAN_BLOCKS 586   // ceil(NTOT/256)

// Scratch (allocation-free: __device__ globals)
__device__ float  d_buf1[NTOT * D];
__device__ float  d_buf2[NTOT * D];
__device__ float  d_buf3[NTOT * D];
__device__ int    d_cnt [NTOT];
__device__ int    d_cur [NTOT];
__device__ int    d_rs  [NTOT + 1];
__device__ int    d_bsum[SCAN_BLOCKS];
__device__ int    d_boff[SCAN_BLOCKS];
__device__ float2 d_scv [NNZ];          // packed (col_as_float_bits, val)

// ---------------------------------------------------------------------------
// zero row counters
// ---------------------------------------------------------------------------
__global__ void zero_kernel() {
    int i = blockIdx.x * blockDim.x + threadIdx.x;
    if (i < NTOT) d_cnt[i] = 0;
}

// ---------------------------------------------------------------------------
// histogram of rows (4 edges per thread, vectorized load)
// ---------------------------------------------------------------------------
__global__ void hist_kernel(const int4* __restrict__ grow4) {
    int i = blockIdx.x * blockDim.x + threadIdx.x;   // NNZ/4 threads
    if (i >= NNZ / 4) return;
    int4 r = grow4[i];
    atomicAdd(&d_cnt[r.x], 1);
    atomicAdd(&d_cnt[r.y], 1);
    atomicAdd(&d_cnt[r.z], 1);
    atomicAdd(&d_cnt[r.w], 1);
}

// ---------------------------------------------------------------------------
// scan stage 1: per-block exclusive scan of d_cnt -> d_rs, block sums -> d_bsum
// ---------------------------------------------------------------------------
__global__ void scan1_kernel() {
    __shared__ int ws[8];
    int i = blockIdx.x * 256 + threadIdx.x;
    int lane = threadIdx.x & 31, w = threadIdx.x >> 5;
    int c = (i < NTOT) ? d_cnt[i] : 0;
    int x = c;
    #pragma unroll
    for (int o = 1; o < 32; o <<= 1) {
        int y = __shfl_up_sync(0xffffffffu, x, o);
        if (lane >= o) x += y;
    }
    if (lane == 31) ws[w] = x;
    __syncthreads();
    if (w == 0) {                         // whole warp participates
        int s = (lane < 8) ? ws[lane] : 0;
        #pragma unroll
        for (int o = 1; o < 8; o <<= 1) {
            int y = __shfl_up_sync(0xffffffffu, s, o);
            if (lane >= o) s += y;
        }
        if (lane < 8) ws[lane] = s;
    }
    __syncthreads();
    int off = (w > 0) ? ws[w - 1] : 0;
    int incl = x + off;
    if (i < NTOT) d_rs[i] = incl - c;
    if (threadIdx.x == 255) d_bsum[blockIdx.x] = incl;
}

// ---------------------------------------------------------------------------
// scan stage 2: ONE block, 640 threads — smem two-level scan of 586 sums
// ---------------------------------------------------------------------------
__global__ void scan2_kernel() {
    __shared__ int ws[20];
    int tid = threadIdx.x;           // 640 threads = 20 warps
    int lane = tid & 31, w = tid >> 5;
    int v = (tid < SCAN_BLOCKS) ? d_bsum[tid] : 0;
    int x = v;
    #pragma unroll
    for (int o = 1; o < 32; o <<= 1) {
        int y = __shfl_up_sync(0xffffffffu, x, o);
        if (lane >= o) x += y;
    }
    if (lane == 31) ws[w] = x;
    __syncthreads();
    if (w == 0) {                         // FULL warp executes (fix for R3 hang)
        int s = (lane < 20) ? ws[lane] : 0;
        #pragma unroll
        for (int o = 1; o < 32; o <<= 1) {
            int y = __shfl_up_sync(0xffffffffu, s, o);
            if (lane >= o) s += y;
        }
        if (lane < 20) ws[lane] = s;
    }
    __syncthreads();
    int off = (w > 0) ? ws[w - 1] : 0;
    if (tid < SCAN_BLOCKS) d_boff[tid] = off + x - v;   // exclusive
    if (tid == SCAN_BLOCKS - 1) d_rs[NTOT] = off + x;   // total == NNZ
}

// ---------------------------------------------------------------------------
// scan stage 3: add block offsets; initialize running cursor d_cur = d_rs
// ---------------------------------------------------------------------------
__global__ void scan3_kernel() {
    int i = blockIdx.x * 256 + threadIdx.x;
    if (i < NTOT) {
        int v = d_rs[i] + d_boff[blockIdx.x];
        d_rs[i]  = v;
        d_cur[i] = v;
    }
}

// ---------------------------------------------------------------------------
// permute edges into CSR order (4 edges per thread, vectorized loads)
// ---------------------------------------------------------------------------
__global__ void permute_kernel(const int4*   __restrict__ grow4,
                               const int4*   __restrict__ gcol4,
                               const float4* __restrict__ gval4) {
    int i = blockIdx.x * blockDim.x + threadIdx.x;
    if (i >= NNZ / 4) return;
    int4   r = grow4[i];
    int4   c = gcol4[i];
    float4 v = gval4[i];
    int p0 = atomicAdd(&d_cur[r.x], 1);
    int p1 = atomicAdd(&d_cur[r.y], 1);
    int p2 = atomicAdd(&d_cur[r.z], 1);
    int p3 = atomicAdd(&d_cur[r.w], 1);
    d_scv[p0] = make_float2(__int_as_float(c.x), v.x);
    d_scv[p1] = make_float2(__int_as_float(c.y), v.y);
    d_scv[p2] = make_float2(__int_as_float(c.z), v.z);
    d_scv[p3] = make_float2(__int_as_float(c.w), v.w);
}

// ---------------------------------------------------------------------------
// Gather SpMM: one row per 16 lanes, one float4 per lane, edge loop x4 unroll.
// ---------------------------------------------------------------------------
__device__ __forceinline__ const float4* src_ptr(const float4* xu,
                                                 const float4* xi, int c) {
    return (c < N_USERS) ? (xu + (size_t)c * 16)
                         : (xi + (size_t)(c - N_USERS) * 16);
}

__global__ void spmm_gather_kernel(const float4* __restrict__ xu,
                                   const float4* __restrict__ xi,
                                   float4*       __restrict__ xout) {
    int gid = blockIdx.x * blockDim.x + threadIdx.x;
    int row = gid >> 4;
    int t   = gid & 15;
    if (row >= NTOT) return;
    int s = d_rs[row], e = d_rs[row + 1];
    float4 a = make_float4(0.f, 0.f, 0.f, 0.f);
    int i = s;
    for (; i + 4 <= e; i += 4) {
        float2 p0 = d_scv[i],     p1 = d_scv[i + 1];
        float2 p2 = d_scv[i + 2], p3 = d_scv[i + 3];
        float4 x0 = src_ptr(xu, xi, __float_as_int(p0.x))[t];
        float4 x1 = src_ptr(xu, xi, __float_as_int(p1.x))[t];
        float4 x2 = src_ptr(xu, xi, __float_as_int(p2.x))[t];
        float4 x3 = src_ptr(xu, xi, __float_as_int(p3.x))[t];
        a.x += p0.y * x0.x; a.y += p0.y * x0.y; a.z += p0.y * x0.z; a.w += p0.y * x0.w;
        a.x += p1.y * x1.x; a.y += p1.y * x1.y; a.z += p1.y * x1.z; a.w += p1.y * x1.w;
        a.x += p2.y * x2.x; a.y += p2.y * x2.y; a.z += p2.y * x2.z; a.w += p2.y * x2.w;
        a.x += p3.y * x3.x; a.y += p3.y * x3.y; a.z += p3.y * x3.z; a.w += p3.y * x3.w;
    }
    for (; i < e; i++) {
        float2 p = d_scv[i];
        float4 x = src_ptr(xu, xi, __float_as_int(p.x))[t];
        a.x += p.y * x.x; a.y += p.y * x.y; a.z += p.y * x.z; a.w += p.y * x.w;
    }
    xout[(size_t)row * 16 + t] = a;
}

// ---------------------------------------------------------------------------
// Tail: light[row] = (emb[row] + b1 + b2 + b3) / 4 at gathered rows,
// two 64x64 matvecs, softmax/sigmoid, dot. One warp per batch element.
// ---------------------------------------------------------------------------
__global__ void final_kernel(const float* __restrict__ eu,
                             const float* __restrict__ ei,
                             const float* __restrict__ w_user,
                             const float* __restrict__ w_item,
                             const float* __restrict__ xe1,
                             const float* __restrict__ xe0,
                             const int*   __restrict__ users,
                             const int*   __restrict__ items,
                             const int*   __restrict__ xij,
                             float*       __restrict__ out) {
    __shared__ float wu[64 * 65];
    __shared__ float wi[64 * 65];
    int tid = threadIdx.x;                     // 128 threads
    for (int idx = tid; idx < 64 * 64; idx += blockDim.x) {
        int r = idx >> 6, c = idx & 63;
        wu[r * 65 + c] = w_user[idx];
        wi[r * 65 + c] = w_item[idx];
    }
    __syncthreads();

    int warp = tid >> 5;
    int lane = tid & 31;

    int b_base = blockIdx.x * 32 + warp * 8;   // 512 blocks * 4 warps * 8
    for (int bi = 0; bi < 8; bi++) {
        int b = b_base + bi;
        int u  = users[b];
        int it = items[b];
        size_t uo = (size_t)u * 64;
        size_t io = (size_t)(N_USERS + it) * 64;
        size_t ie_off = (size_t)it * 64;

        float ue0 = (eu[uo + lane] + d_buf1[uo + lane] +
                     d_buf2[uo + lane] + d_buf3[uo + lane]) * 0.25f;
        float ue1 = (eu[uo + 32 + lane] + d_buf1[uo + 32 + lane] +
                     d_buf2[uo + 32 + lane] + d_buf3[uo + 32 + lane]) * 0.25f;
        float ie0 = (ei[ie_off + lane] + d_buf1[io + lane] +
                     d_buf2[io + lane] + d_buf3[io + lane]) * 0.25f;
        float ie1 = (ei[ie_off + 32 + lane] + d_buf1[io + 32 + lane] +
                     d_buf2[io + 32 + lane] + d_buf3[io + 32 + lane]) * 0.25f;

        float po0 = 0.f, po1 = 0.f, qo0 = 0.f, qo1 = 0.f;
        #pragma unroll
        for (int k = 0; k < 32; k++) {
            float au = __shfl_sync(0xffffffffu, ue0, k);
            float ai = __shfl_sync(0xffffffffu, ie0, k);
            po0 += au * wu[lane * 65 + k];
            po1 += au * wu[(lane + 32) * 65 + k];
            qo0 += ai * wi[lane * 65 + k];
            qo1 += ai * wi[(lane + 32) * 65 + k];
        }
        #pragma unroll
        for (int k = 0; k < 32; k++) {
            float au = __shfl_sync(0xffffffffu, ue1, k);
            float ai = __shfl_sync(0xffffffffu, ie1, k);
            po0 += au * wu[lane * 65 + 32 + k];
            po1 += au * wu[(lane + 32) * 65 + 32 + k];
            qo0 += ai * wi[lane * 65 + 32 + k];
            qo1 += ai * wi[(lane + 32) * 65 + 32 + k];
        }

        float m = fmaxf(po0, po1);
        #pragma unroll
        for (int o = 16; o; o >>= 1)
            m = fmaxf(m, __shfl_xor_sync(0xffffffffu, m, o));
        float e0 = expf(po0 - m);
        float e1 = expf(po1 - m);
        float s = e0 + e1;
        #pragma unroll
        for (int o = 16; o; o >>= 1)
            s += __shfl_xor_sync(0xffffffffu, s, o);
        float scale = 0.5f / s;                 // (1 - hx) * softmax

        float sg0 = 1.f / (1.f + expf(-qo0));
        float sg1 = 1.f / (1.f + expf(-qo1));

        float part = scale * (e0 * sg0 + e1 * sg1);
        #pragma unroll
        for (int o = 16; o; o >>= 1)
            part += __shfl_xor_sync(0xffffffffu, part, o);

        if (lane == 0) {
            float xe  = (xij[b] > 0) ? xe1[it] : xe0[it];
            float sgx = 1.f / (1.f + expf(-xe));
            out[b] = part + 0.5f * sgx;
        }
    }
}

// ---------------------------------------------------------------------------
extern "C" void kernel_launch(void* const* d_in, const int* in_sizes, int n_in,
                              void* d_out, int out_size) {
    (void)in_sizes; (void)n_in; (void)out_size;
    const float* emb_user = (const float*)d_in[0];
    const float* emb_item = (const float*)d_in[1];
    const float* w_user   = (const float*)d_in[2];
    const float* w_item   = (const float*)d_in[3];
    const float* xe1      = (const float*)d_in[4];
    const float* xe0      = (const float*)d_in[5];
    const float* g_val    = (const float*)d_in[6];
    const int*   g_row    = (const int*)d_in[7];
    const int*   g_col    = (const int*)d_in[8];
    const int*   users    = (const int*)d_in[9];
    const int*   items    = (const int*)d_in[10];
    const int*   xij      = (const int*)d_in[11];
    float* out = (float*)d_out;

    float *p_buf1, *p_buf2, *p_buf3;
    cudaGetSymbolAddress((void**)&p_buf1, d_buf1);
    cudaGetSymbolAddress((void**)&p_buf2, d_buf2);
    cudaGetSymbolAddress((void**)&p_buf3, d_buf3);

    const int nnz4Blocks   = (NNZ / 4 + 255) / 256;
    const int gatherBlocks = (NTOT * 16 + 255) / 256;

    // CSR build
    zero_kernel<<<SCAN_BLOCKS, 256>>>();
    hist_kernel<<<nnz4Blocks, 256>>>((const int4*)g_row);
    scan1_kernel<<<SCAN_BLOCKS, 256>>>();
    scan2_kernel<<<1, 640>>>();
    scan3_kernel<<<SCAN_BLOCKS, 256>>>();
    permute_kernel<<<nnz4Blocks, 256>>>((const int4*)g_row, (const int4*)g_col,
                                        (const float4*)g_val);

    // 3 propagation layers (gather, no atomics, no zeroing)
    spmm_gather_kernel<<<gatherBlocks, 256>>>(
        (const float4*)emb_user, (const float4*)emb_item, (float4*)p_buf1);
    spmm_gather_kernel<<<gatherBlocks, 256>>>(
        (const float4*)p_buf1, (const float4*)p_buf1 + (size_t)N_USERS * 16,
        (float4*)p_buf2);
    spmm_gather_kernel<<<gatherBlocks, 256>>>(
        (const float4*)p_buf2, (const float4*)p_buf2 + (size_t)N_USERS * 16,
        (float4*)p_buf3);

    final_kernel<<<BATCH / 32, 128>>>(emb_user, emb_item, w_user, w_item,
                                      xe1, xe0, users, items, xij, out);
}

// round 5
// speedup vs baseline: 2.3041x; 1.1733x over previous
#include <cuda_runtime.h>
#include <cuda_fp16.h>

#define N_USERS 100000
#define N_ITEMS 50000
#define NTOT    150000
#define D       64
#define NNZ     2000000
#define BATCH   16384
#define SCAN_BLOCKS 586   // ceil(NTOT/256)

// Scratch (allocation-free: __device__ globals)
__device__ __half  d_h0[NTOT * D];      // fp16 copy of concat(emb_user, emb_item)
__device__ __half  d_h1[NTOT * D];      // layer 1 output (fp16)
__device__ __half  d_h2[NTOT * D];      // layer 2 output (fp16)
__device__ float   d_b3[NTOT * D];      // layer 3 output (fp32, never gathered)
__device__ int     d_cnt [NTOT];
__device__ int     d_cur [NTOT];
__device__ int     d_rs  [NTOT + 1];
__device__ int     d_bsum[SCAN_BLOCKS];
__device__ int     d_boff[SCAN_BLOCKS];
__device__ float2  d_scv [NNZ];         // packed (col_as_float_bits, val)

// ---------------------------------------------------------------------------
// convert embeddings to fp16: d_h0 = half(concat(eu, ei))
// one thread = 8 elements (two float4 loads -> one uint4 store)
// ---------------------------------------------------------------------------
__global__ void tohalf_kernel(const float4* __restrict__ eu,
                              const float4* __restrict__ ei) {
    int i = blockIdx.x * blockDim.x + threadIdx.x;    // chunk of 8 elements
    const int total8 = NTOT * D / 8;
    if (i >= total8) return;
    const int uhalf = N_USERS * D / 8;
    float4 a, b;
    if (i < uhalf) { a = eu[i * 2]; b = eu[i * 2 + 1]; }
    else { int j = i - uhalf; a = ei[j * 2]; b = ei[j * 2 + 1]; }
    __half2 h[4];
    h[0] = __floats2half2_rn(a.x, a.y);
    h[1] = __floats2half2_rn(a.z, a.w);
    h[2] = __floats2half2_rn(b.x, b.y);
    h[3] = __floats2half2_rn(b.z, b.w);
    ((uint4*)d_h0)[i] = *(uint4*)h;
}

// ---------------------------------------------------------------------------
// histogram of rows (4 edges per thread, vectorized load)
// d_cnt is zero on entry (zero-init at load; reset by scan1 each launch)
// ---------------------------------------------------------------------------
__global__ void hist_kernel(const int4* __restrict__ grow4) {
    int i = blockIdx.x * blockDim.x + threadIdx.x;
    if (i >= NNZ / 4) return;
    int4 r = grow4[i];
    atomicAdd(&d_cnt[r.x], 1);
    atomicAdd(&d_cnt[r.y], 1);
    atomicAdd(&d_cnt[r.z], 1);
    atomicAdd(&d_cnt[r.w], 1);
}

// ---------------------------------------------------------------------------
// scan stage 1: per-block exclusive scan of d_cnt -> d_rs, block sums.
// Also resets d_cnt to 0 for the next graph replay.
// ---------------------------------------------------------------------------
__global__ void scan1_kernel() {
    __shared__ int ws[8];
    int i = blockIdx.x * 256 + threadIdx.x;
    int lane = threadIdx.x & 31, w = threadIdx.x >> 5;
    int c = (i < NTOT) ? d_cnt[i] : 0;
    if (i < NTOT) d_cnt[i] = 0;
    int x = c;
    #pragma unroll
    for (int o = 1; o < 32; o <<= 1) {
        int y = __shfl_up_sync(0xffffffffu, x, o);
        if (lane >= o) x += y;
    }
    if (lane == 31) ws[w] = x;
    __syncthreads();
    if (w == 0) {
        int s = (lane < 8) ? ws[lane] : 0;
        #pragma unroll
        for (int o = 1; o < 8; o <<= 1) {
            int y = __shfl_up_sync(0xffffffffu, s, o);
            if (lane >= o) s += y;
        }
        if (lane < 8) ws[lane] = s;
    }
    __syncthreads();
    int off = (w > 0) ? ws[w - 1] : 0;
    int incl = x + off;
    if (i < NTOT) d_rs[i] = incl - c;
    if (threadIdx.x == 255) d_bsum[blockIdx.x] = incl;
}

// ---------------------------------------------------------------------------
// scan stage 2: ONE block, 640 threads — two-level scan of 586 sums
// ---------------------------------------------------------------------------
__global__ void scan2_kernel() {
    __shared__ int ws[20];
    int tid = threadIdx.x;           // 640 threads = 20 warps
    int lane = tid & 31, w = tid >> 5;
    int v = (tid < SCAN_BLOCKS) ? d_bsum[tid] : 0;
    int x = v;
    #pragma unroll
    for (int o = 1; o < 32; o <<= 1) {
        int y = __shfl_up_sync(0xffffffffu, x, o);
        if (lane >= o) x += y;
    }
    if (lane == 31) ws[w] = x;
    __syncthreads();
    if (w == 0) {                    // full warp executes (no partial-mask hang)
        int s = (lane < 20) ? ws[lane] : 0;
        #pragma unroll
        for (int o = 1; o < 32; o <<= 1) {
            int y = __shfl_up_sync(0xffffffffu, s, o);
            if (lane >= o) s += y;
        }
        if (lane < 20) ws[lane] = s;
    }
    __syncthreads();
    int off = (w > 0) ? ws[w - 1] : 0;
    if (tid < SCAN_BLOCKS) d_boff[tid] = off + x - v;
    if (tid == SCAN_BLOCKS - 1) d_rs[NTOT] = off + x;
}

// ---------------------------------------------------------------------------
// scan stage 3: add block offsets; initialize running cursor d_cur = d_rs
// ---------------------------------------------------------------------------
__global__ void scan3_kernel() {
    int i = blockIdx.x * 256 + threadIdx.x;
    if (i < NTOT) {
        int v = d_rs[i] + d_boff[blockIdx.x];
        d_rs[i]  = v;
        d_cur[i] = v;
    }
}

// ---------------------------------------------------------------------------
// permute edges into CSR order (4 edges per thread, vectorized loads)
// ---------------------------------------------------------------------------
__global__ void permute_kernel(const int4*   __restrict__ grow4,
                               const int4*   __restrict__ gcol4,
                               const float4* __restrict__ gval4) {
    int i = blockIdx.x * blockDim.x + threadIdx.x;
    if (i >= NNZ / 4) return;
    int4   r = grow4[i];
    int4   c = gcol4[i];
    float4 v = gval4[i];
    int p0 = atomicAdd(&d_cur[r.x], 1);
    int p1 = atomicAdd(&d_cur[r.y], 1);
    int p2 = atomicAdd(&d_cur[r.z], 1);
    int p3 = atomicAdd(&d_cur[r.w], 1);
    d_scv[p0] = make_float2(__int_as_float(c.x), v.x);
    d_scv[p1] = make_float2(__int_as_float(c.y), v.y);
    d_scv[p2] = make_float2(__int_as_float(c.z), v.z);
    d_scv[p3] = make_float2(__int_as_float(c.w), v.w);
}

// ---------------------------------------------------------------------------
// Gather SpMM over fp16 features, fp32 accumulation.
// One row per 8 lanes; each lane owns 8 halves (one uint4 = 16B). x4 unroll.
// OUT = __half (layers 1,2) or float (layer 3).
// ---------------------------------------------------------------------------
__device__ __forceinline__ void fma8(float* a, uint4 x, float v) {
    const __half2* h = (const __half2*)&x;
    #pragma unroll
    for (int j = 0; j < 4; j++) {
        float2 f = __half22float2(h[j]);
        a[2 * j]     += v * f.x;
        a[2 * j + 1] += v * f.y;
    }
}

template <typename OUT>
__global__ void spmm_gather_h(const __half* __restrict__ xin,
                              OUT*          __restrict__ xout) {
    int gid = blockIdx.x * blockDim.x + threadIdx.x;
    int row = gid >> 3;
    int t   = gid & 7;
    if (row >= NTOT) return;
    int s = d_rs[row], e = d_rs[row + 1];
    const uint4* feat = (const uint4*)xin;      // 8 uint4 per row
    float a[8] = {0.f, 0.f, 0.f, 0.f, 0.f, 0.f, 0.f, 0.f};
    int i = s;
    for (; i + 4 <= e; i += 4) {
        float2 p0 = d_scv[i],     p1 = d_scv[i + 1];
        float2 p2 = d_scv[i + 2], p3 = d_scv[i + 3];
        uint4 x0 = feat[(size_t)__float_as_int(p0.x) * 8 + t];
        uint4 x1 = feat[(size_t)__float_as_int(p1.x) * 8 + t];
        uint4 x2 = feat[(size_t)__float_as_int(p2.x) * 8 + t];
        uint4 x3 = feat[(size_t)__float_as_int(p3.x) * 8 + t];
        fma8(a, x0, p0.y);
        fma8(a, x1, p1.y);
        fma8(a, x2, p2.y);
        fma8(a, x3, p3.y);
    }
    for (; i < e; i++) {
        float2 p = d_scv[i];
        uint4 x = feat[(size_t)__float_as_int(p.x) * 8 + t];
        fma8(a, x, p.y);
    }
    size_t base = (size_t)row * 64 + t * 8;
    if (sizeof(OUT) == 2) {                     // fp16 output
        __half2 o[4];
        #pragma unroll
        for (int j = 0; j < 4; j++)
            o[j] = __floats2half2_rn(a[2 * j], a[2 * j + 1]);
        *(uint4*)((__half*)xout + base) = *(uint4*)o;
    } else {                                    // fp32 output
        float4 o0 = make_float4(a[0], a[1], a[2], a[3]);
        float4 o1 = make_float4(a[4], a[5], a[6], a[7]);
        *(float4*)((float*)xout + base)     = o0;
        *(float4*)((float*)xout + base + 4) = o1;
    }
}

// ---------------------------------------------------------------------------
// Tail: light = (emb + h1 + h2 + b3) / 4 at gathered rows, two 64x64 matvecs,
// softmax/sigmoid, dot. One warp per batch element.
// ---------------------------------------------------------------------------
__global__ void final_kernel(const float* __restrict__ eu,
                             const float* __restrict__ ei,
                             const float* __restrict__ w_user,
                             const float* __restrict__ w_item,
                             const float* __restrict__ xe1,
                             const float* __restrict__ xe0,
                             const int*   __restrict__ users,
                             const int*   __restrict__ items,
                             const int*   __restrict__ xij,
                             float*       __restrict__ out) {
    __shared__ float wu[64 * 65];
    __shared__ float wi[64 * 65];
    int tid = threadIdx.x;                     // 128 threads
    for (int idx = tid; idx < 64 * 64; idx += blockDim.x) {
        int r = idx >> 6, c = idx & 63;
        wu[r * 65 + c] = w_user[idx];
        wi[r * 65 + c] = w_item[idx];
    }
    __syncthreads();

    int warp = tid >> 5;
    int lane = tid & 31;

    int b_base = blockIdx.x * 32 + warp * 8;   // 512 blocks * 4 warps * 8
    for (int bi = 0; bi < 8; bi++) {
        int b = b_base + bi;
        int u  = users[b];
        int it = items[b];
        size_t uo = (size_t)u * 64;
        size_t io = (size_t)(N_USERS + it) * 64;
        size_t ie_off = (size_t)it * 64;

        float ue0 = (eu[uo + lane] + __half2float(d_h1[uo + lane]) +
                     __half2float(d_h2[uo + lane]) + d_b3[uo + lane]) * 0.25f;
        float ue1 = (eu[uo + 32 + lane] + __half2float(d_h1[uo + 32 + lane]) +
                     __half2float(d_h2[uo + 32 + lane]) + d_b3[uo + 32 + lane]) * 0.25f;
        float ie0 = (ei[ie_off + lane] + __half2float(d_h1[io + lane]) +
                     __half2float(d_h2[io + lane]) + d_b3[io + lane]) * 0.25f;
        float ie1 = (ei[ie_off + 32 + lane] + __half2float(d_h1[io + 32 + lane]) +
                     __half2float(d_h2[io + 32 + lane]) + d_b3[io + 32 + lane]) * 0.25f;

        float po0 = 0.f, po1 = 0.f, qo0 = 0.f, qo1 = 0.f;
        #pragma unroll
        for (int k = 0; k < 32; k++) {
            float au = __shfl_sync(0xffffffffu, ue0, k);
            float ai = __shfl_sync(0xffffffffu, ie0, k);
            po0 += au * wu[lane * 65 + k];
            po1 += au * wu[(lane + 32) * 65 + k];
            qo0 += ai * wi[lane * 65 + k];
            qo1 += ai * wi[(lane + 32) * 65 + k];
        }
        #pragma unroll
        for (int k = 0; k < 32; k++) {
            float au = __shfl_sync(0xffffffffu, ue1, k);
            float ai = __shfl_sync(0xffffffffu, ie1, k);
            po0 += au * wu[lane * 65 + 32 + k];
            po1 += au * wu[(lane + 32) * 65 + 32 + k];
            qo0 += ai * wi[lane * 65 + 32 + k];
            qo1 += ai * wi[(lane + 32) * 65 + 32 + k];
        }

        float m = fmaxf(po0, po1);
        #pragma unroll
        for (int o = 16; o; o >>= 1)
            m = fmaxf(m, __shfl_xor_sync(0xffffffffu, m, o));
        float e0 = expf(po0 - m);
        float e1 = expf(po1 - m);
        float s = e0 + e1;
        #pragma unroll
        for (int o = 16; o; o >>= 1)
            s += __shfl_xor_sync(0xffffffffu, s, o);
        float scale = 0.5f / s;                 // (1 - hx) * softmax

        float sg0 = 1.f / (1.f + expf(-qo0));
        float sg1 = 1.f / (1.f + expf(-qo1));

        float part = scale * (e0 * sg0 + e1 * sg1);
        #pragma unroll
        for (int o = 16; o; o >>= 1)
            part += __shfl_xor_sync(0xffffffffu, part, o);

        if (lane == 0) {
            float xe  = (xij[b] > 0) ? xe1[it] : xe0[it];
            float sgx = 1.f / (1.f + expf(-xe));
            out[b] = part + 0.5f * sgx;
        }
    }
}

// ---------------------------------------------------------------------------
extern "C" void kernel_launch(void* const* d_in, const int* in_sizes, int n_in,
                              void* d_out, int out_size) {
    (void)in_sizes; (void)n_in; (void)out_size;
    const float* emb_user = (const float*)d_in[0];
    const float* emb_item = (const float*)d_in[1];
    const float* w_user   = (const float*)d_in[2];
    const float* w_item   = (const float*)d_in[3];
    const float* xe1      = (const float*)d_in[4];
    const float* xe0      = (const float*)d_in[5];
    const float* g_val    = (const float*)d_in[6];
    const int*   g_row    = (const int*)d_in[7];
    const int*   g_col    = (const int*)d_in[8];
    const int*   users    = (const int*)d_in[9];
    const int*   items    = (const int*)d_in[10];
    const int*   xij      = (const int*)d_in[11];
    float* out = (float*)d_out;

    __half *p_h0, *p_h1, *p_h2;
    float  *p_b3;
    cudaGetSymbolAddress((void**)&p_h0, d_h0);
    cudaGetSymbolAddress((void**)&p_h1, d_h1);
    cudaGetSymbolAddress((void**)&p_h2, d_h2);
    cudaGetSymbolAddress((void**)&p_b3, d_b3);

    const int nnz4Blocks   = (NNZ / 4 + 255) / 256;
    const int convBlocks   = (NTOT * D / 8 + 255) / 256;
    const int gatherBlocks = (NTOT * 8 + 255) / 256;

    // CSR build + fp16 conversion (d_cnt is zeroed by scan1 of previous launch)
    tohalf_kernel<<<convBlocks, 256>>>((const float4*)emb_user,
                                       (const float4*)emb_item);
    hist_kernel<<<nnz4Blocks, 256>>>((const int4*)g_row);
    scan1_kernel<<<SCAN_BLOCKS, 256>>>();
    scan2_kernel<<<1, 640>>>();
    scan3_kernel<<<SCAN_BLOCKS, 256>>>();
    permute_kernel<<<nnz4Blocks, 256>>>((const int4*)g_row, (const int4*)g_col,
                                        (const float4*)g_val);

    // 3 propagation layers (fp16 gather, fp32 accumulate)
    spmm_gather_h<__half><<<gatherBlocks, 256>>>(p_h0, p_h1);
    spmm_gather_h<__half><<<gatherBlocks, 256>>>(p_h1, p_h2);
    spmm_gather_h<float ><<<gatherBlocks, 256>>>(p_h2, p_b3);

    final_kernel<<<BATCH / 32, 128>>>(emb_user, emb_item, w_user, w_item,
                                      xe1, xe0, users, items, xij, out);
}

// round 6
// speedup vs baseline: 2.3048x; 1.0003x over previous
#include <cuda_runtime.h>
#include <cuda_fp16.h>

#define N_USERS 100000
#define N_ITEMS 50000
#define NTOT    150000
#define D       64
#define NNZ     2000000
#define BATCH   16384
#define NTILES  586            // ceil(NTOT/256)
#define CONV_BLOCKS 4688       // NTOT*D/8/256
#define HIST_BLOCKS 1954       // ceil(NNZ/4/256)

// Scratch (allocation-free: __device__ globals; zero-initialized at load)
__device__ __half  d_h0[NTOT * D];      // fp16 concat(emb_user, emb_item)
__device__ __half  d_h1[NTOT * D];      // layer 1 output (fp16)
__device__ __half  d_h2[NTOT * D];      // layer 2 output (fp16)
__device__ float   d_b3[NTOT * D];      // layer 3 output (fp32, never gathered)
__device__ int     d_cnt [NTOT];
__device__ int     d_cur [NTOT];
__device__ int     d_rs  [NTOT + 1];
__device__ unsigned long long d_tstate[NTILES];  // lookback states: flag<<32|val
__device__ float2  d_scv [NNZ];         // packed (col_as_float_bits, val)

// ---------------------------------------------------------------------------
// k1 (fused): tohalf | histogram | lookback-state reset
//   blocks [0, CONV_BLOCKS)                : fp16 conversion
//   blocks [CONV_BLOCKS, CONV+HIST)        : row histogram (d_cnt, zero on entry)
//   blocks [CONV+HIST, CONV+HIST+3)        : reset d_tstate (flags -> 0)
// ---------------------------------------------------------------------------
__global__ void k1_fused(const float4* __restrict__ eu,
                         const float4* __restrict__ ei,
                         const int4*   __restrict__ grow4) {
    int bid = blockIdx.x;
    if (bid < CONV_BLOCKS) {
        int i = bid * 256 + threadIdx.x;            // chunk of 8 elements
        const int total8 = NTOT * D / 8;
        if (i >= total8) return;
        const int uhalf = N_USERS * D / 8;
        float4 a, b;
        if (i < uhalf) { a = eu[i * 2]; b = eu[i * 2 + 1]; }
        else { int j = i - uhalf; a = ei[j * 2]; b = ei[j * 2 + 1]; }
        __half2 h[4];
        h[0] = __floats2half2_rn(a.x, a.y);
        h[1] = __floats2half2_rn(a.z, a.w);
        h[2] = __floats2half2_rn(b.x, b.y);
        h[3] = __floats2half2_rn(b.z, b.w);
        ((uint4*)d_h0)[i] = *(uint4*)h;
    } else if (bid < CONV_BLOCKS + HIST_BLOCKS) {
        int i = (bid - CONV_BLOCKS) * 256 + threadIdx.x;
        if (i >= NNZ / 4) return;
        int4 r = grow4[i];
        atomicAdd(&d_cnt[r.x], 1);
        atomicAdd(&d_cnt[r.y], 1);
        atomicAdd(&d_cnt[r.z], 1);
        atomicAdd(&d_cnt[r.w], 1);
    } else {
        int i = (bid - CONV_BLOCKS - HIST_BLOCKS) * 256 + threadIdx.x;
        if (i < NTILES) d_tstate[i] = 0ULL;
    }
}

// ---------------------------------------------------------------------------
// k2: single-pass decoupled-lookback scan of d_cnt -> d_rs (exclusive).
// Also zeroes d_cnt for the next replay and initializes d_cur = d_rs.
// 586 blocks x 256 threads = one wave (co-resident) -> lookback is safe.
// ---------------------------------------------------------------------------
__global__ void k2_scan_lookback() {
    __shared__ int ws[8];
    __shared__ int s_off;
    const int tile = blockIdx.x;
    const int i = tile * 256 + threadIdx.x;
    const int lane = threadIdx.x & 31, w = threadIdx.x >> 5;

    int c = (i < NTOT) ? d_cnt[i] : 0;
    if (i < NTOT) d_cnt[i] = 0;

    // intra-tile inclusive scan
    int x = c;
    #pragma unroll
    for (int o = 1; o < 32; o <<= 1) {
        int y = __shfl_up_sync(0xffffffffu, x, o);
        if (lane >= o) x += y;
    }
    if (lane == 31) ws[w] = x;
    __syncthreads();
    if (w == 0) {                       // full warp, guarded data (no hang)
        int s = (lane < 8) ? ws[lane] : 0;
        #pragma unroll
        for (int o = 1; o < 8; o <<= 1) {
            int y = __shfl_up_sync(0xffffffffu, s, o);
            if (lane >= o) s += y;
        }
        if (lane < 8) ws[lane] = s;
    }
    __syncthreads();
    int woff = (w > 0) ? ws[w - 1] : 0;
    int incl = x + woff;                // inclusive prefix within tile
    int total = ws[7];                  // tile total

    // publish: tile 0 can publish INCLUSIVE immediately
    if (threadIdx.x == 0) {
        unsigned long long st = (tile == 0)
            ? ((2ULL << 32) | (unsigned)total)
            : ((1ULL << 32) | (unsigned)total);
        *(volatile unsigned long long*)&d_tstate[tile] = st;
    }

    // warp-parallel lookback (warp 0)
    if (w == 0) {
        int running = 0;
        int base = tile - 1;
        while (base >= 0) {
            int idx = base - lane;
            unsigned long long st;
            int flag;
            do {
                st = (idx >= 0)
                   ? *(volatile unsigned long long*)&d_tstate[idx]
                   : (2ULL << 32);
                flag = (int)(st >> 32);
            } while (__any_sync(0xffffffffu, flag == 0));
            int val = (int)(unsigned)st;
            unsigned mask = __ballot_sync(0xffffffffu, flag == 2);
            if (mask) {
                int k = __ffs(mask) - 1;          // nearest INCLUSIVE tile
                int contrib = (lane <= k) ? val : 0;
                #pragma unroll
                for (int o = 16; o; o >>= 1)
                    contrib += __shfl_xor_sync(0xffffffffu, contrib, o);
                running += contrib;
                break;
            } else {
                int contrib = val;
                #pragma unroll
                for (int o = 16; o; o >>= 1)
                    contrib += __shfl_xor_sync(0xffffffffu, contrib, o);
                running += contrib;
                base -= 32;
            }
        }
        if (lane == 0) {
            s_off = running;
            if (tile > 0)
                *(volatile unsigned long long*)&d_tstate[tile] =
                    (2ULL << 32) | (unsigned)(running + total);
        }
    }
    __syncthreads();

    int excl = s_off + incl - c;
    if (i <= NTOT) d_rs[i] = excl;      // i==NTOT has c==0 -> writes NNZ total
    if (i < NTOT)  d_cur[i] = excl;
}

// ---------------------------------------------------------------------------
// k3: permute edges into CSR order (4 edges per thread, vectorized loads)
// ---------------------------------------------------------------------------
__global__ void k3_permute(const int4*   __restrict__ grow4,
                           const int4*   __restrict__ gcol4,
                           const float4* __restrict__ gval4) {
    int i = blockIdx.x * blockDim.x + threadIdx.x;
    if (i >= NNZ / 4) return;
    int4   r = grow4[i];
    int4   c = gcol4[i];
    float4 v = gval4[i];
    int p0 = atomicAdd(&d_cur[r.x], 1);
    int p1 = atomicAdd(&d_cur[r.y], 1);
    int p2 = atomicAdd(&d_cur[r.z], 1);
    int p3 = atomicAdd(&d_cur[r.w], 1);
    d_scv[p0] = make_float2(__int_as_float(c.x), v.x);
    d_scv[p1] = make_float2(__int_as_float(c.y), v.y);
    d_scv[p2] = make_float2(__int_as_float(c.z), v.z);
    d_scv[p3] = make_float2(__int_as_float(c.w), v.w);
}

// ---------------------------------------------------------------------------
// Gather SpMM over fp16 features, fp32 accumulation.
// One row per 8 lanes; each lane owns 8 halves (one uint4 = 16B). x4 unroll.
// ---------------------------------------------------------------------------
__device__ __forceinline__ void fma8(float* a, uint4 x, float v) {
    const __half2* h = (const __half2*)&x;
    #pragma unroll
    for (int j = 0; j < 4; j++) {
        float2 f = __half22float2(h[j]);
        a[2 * j]     += v * f.x;
        a[2 * j + 1] += v * f.y;
    }
}

template <typename OUT>
__global__ void spmm_gather_h(const __half* __restrict__ xin,
                              OUT*          __restrict__ xout) {
    int gid = blockIdx.x * blockDim.x + threadIdx.x;
    int row = gid >> 3;
    int t   = gid & 7;
    if (row >= NTOT) return;
    int s = d_rs[row], e = d_rs[row + 1];
    const uint4* feat = (const uint4*)xin;      // 8 uint4 per row
    float a[8] = {0.f, 0.f, 0.f, 0.f, 0.f, 0.f, 0.f, 0.f};
    int i = s;
    for (; i + 4 <= e; i += 4) {
        float2 p0 = d_scv[i],     p1 = d_scv[i + 1];
        float2 p2 = d_scv[i + 2], p3 = d_scv[i + 3];
        uint4 x0 = feat[(size_t)__float_as_int(p0.x) * 8 + t];
        uint4 x1 = feat[(size_t)__float_as_int(p1.x) * 8 + t];
        uint4 x2 = feat[(size_t)__float_as_int(p2.x) * 8 + t];
        uint4 x3 = feat[(size_t)__float_as_int(p3.x) * 8 + t];
        fma8(a, x0, p0.y);
        fma8(a, x1, p1.y);
        fma8(a, x2, p2.y);
        fma8(a, x3, p3.y);
    }
    for (; i < e; i++) {
        float2 p = d_scv[i];
        uint4 x = feat[(size_t)__float_as_int(p.x) * 8 + t];
        fma8(a, x, p.y);
    }
    size_t base = (size_t)row * 64 + t * 8;
    if (sizeof(OUT) == 2) {                     // fp16 output
        __half2 o[4];
        #pragma unroll
        for (int j = 0; j < 4; j++)
            o[j] = __floats2half2_rn(a[2 * j], a[2 * j + 1]);
        *(uint4*)((__half*)xout + base) = *(uint4*)o;
    } else {                                    // fp32 output
        float4 o0 = make_float4(a[0], a[1], a[2], a[3]);
        float4 o1 = make_float4(a[4], a[5], a[6], a[7]);
        *(float4*)((float*)xout + base)     = o0;
        *(float4*)((float*)xout + base + 4) = o1;
    }
}

// ---------------------------------------------------------------------------
// Tail: light = (emb + h1 + h2 + b3) / 4 at gathered rows, two 64x64 matvecs,
// softmax/sigmoid, dot. One warp per batch element.
// ---------------------------------------------------------------------------
__global__ void final_kernel(const float* __restrict__ eu,
                             const float* __restrict__ ei,
                             const float* __restrict__ w_user,
                             const float* __restrict__ w_item,
                             const float* __restrict__ xe1,
                             const float* __restrict__ xe0,
                             const int*   __restrict__ users,
                             const int*   __restrict__ items,
                             const int*   __restrict__ xij,
                             float*       __restrict__ out) {
    __shared__ float wu[64 * 65];
    __shared__ float wi[64 * 65];
    int tid = threadIdx.x;                     // 128 threads
    for (int idx = tid; idx < 64 * 64; idx += blockDim.x) {
        int r = idx >> 6, c = idx & 63;
        wu[r * 65 + c] = w_user[idx];
        wi[r * 65 + c] = w_item[idx];
    }
    __syncthreads();

    int warp = tid >> 5;
    int lane = tid & 31;

    int b_base = blockIdx.x * 32 + warp * 8;   // 512 blocks * 4 warps * 8
    for (int bi = 0; bi < 8; bi++) {
        int b = b_base + bi;
        int u  = users[b];
        int it = items[b];
        size_t uo = (size_t)u * 64;
        size_t io = (size_t)(N_USERS + it) * 64;
        size_t ie_off = (size_t)it * 64;

        float ue0 = (eu[uo + lane] + __half2float(d_h1[uo + lane]) +
                     __half2float(d_h2[uo + lane]) + d_b3[uo + lane]) * 0.25f;
        float ue1 = (eu[uo + 32 + lane] + __half2float(d_h1[uo + 32 + lane]) +
                     __half2float(d_h2[uo + 32 + lane]) + d_b3[uo + 32 + lane]) * 0.25f;
        float ie0 = (ei[ie_off + lane] + __half2float(d_h1[io + lane]) +
                     __half2float(d_h2[io + lane]) + d_b3[io + lane]) * 0.25f;
        float ie1 = (ei[ie_off + 32 + lane] + __half2float(d_h1[io + 32 + lane]) +
                     __half2float(d_h2[io + 32 + lane]) + d_b3[io + 32 + lane]) * 0.25f;

        float po0 = 0.f, po1 = 0.f, qo0 = 0.f, qo1 = 0.f;
        #pragma unroll
        for (int k = 0; k < 32; k++) {
            float au = __shfl_sync(0xffffffffu, ue0, k);
            float ai = __shfl_sync(0xffffffffu, ie0, k);
            po0 += au * wu[lane * 65 + k];
            po1 += au * wu[(lane + 32) * 65 + k];
            qo0 += ai * wi[lane * 65 + k];
            qo1 += ai * wi[(lane + 32) * 65 + k];
        }
        #pragma unroll
        for (int k = 0; k < 32; k++) {
            float au = __shfl_sync(0xffffffffu, ue1, k);
            float ai = __shfl_sync(0xffffffffu, ie1, k);
            po0 += au * wu[lane * 65 + 32 + k];
            po1 += au * wu[(lane + 32) * 65 + 32 + k];
            qo0 += ai * wi[lane * 65 + 32 + k];
            qo1 += ai * wi[(lane + 32) * 65 + 32 + k];
        }

        float m = fmaxf(po0, po1);
        #pragma unroll
        for (int o = 16; o; o >>= 1)
            m = fmaxf(m, __shfl_xor_sync(0xffffffffu, m, o));
        float e0 = expf(po0 - m);
        float e1 = expf(po1 - m);
        float s = e0 + e1;
        #pragma unroll
        for (int o = 16; o; o >>= 1)
            s += __shfl_xor_sync(0xffffffffu, s, o);
        float scale = 0.5f / s;                 // (1 - hx) * softmax

        float sg0 = 1.f / (1.f + expf(-qo0));
        float sg1 = 1.f / (1.f + expf(-qo1));

        float part = scale * (e0 * sg0 + e1 * sg1);
        #pragma unroll
        for (int o = 16; o; o >>= 1)
            part += __shfl_xor_sync(0xffffffffu, part, o);

        if (lane == 0) {
            float xe  = (xij[b] > 0) ? xe1[it] : xe0[it];
            float sgx = 1.f / (1.f + expf(-xe));
            out[b] = part + 0.5f * sgx;
        }
    }
}

// ---------------------------------------------------------------------------
extern "C" void kernel_launch(void* const* d_in, const int* in_sizes, int n_in,
                              void* d_out, int out_size) {
    (void)in_sizes; (void)n_in; (void)out_size;
    const float* emb_user = (const float*)d_in[0];
    const float* emb_item = (const float*)d_in[1];
    const float* w_user   = (const float*)d_in[2];
    const float* w_item   = (const float*)d_in[3];
    const float* xe1      = (const float*)d_in[4];
    const float* xe0      = (const float*)d_in[5];
    const float* g_val    = (const float*)d_in[6];
    const int*   g_row    = (const int*)d_in[7];
    const int*   g_col    = (const int*)d_in[8];
    const int*   users    = (const int*)d_in[9];
    const int*   items    = (const int*)d_in[10];
    const int*   xij      = (const int*)d_in[11];
    float* out = (float*)d_out;

    __half *p_h0, *p_h1, *p_h2;
    float  *p_b3;
    cudaGetSymbolAddress((void**)&p_h0, d_h0);
    cudaGetSymbolAddress((void**)&p_h1, d_h1);
    cudaGetSymbolAddress((void**)&p_h2, d_h2);
    cudaGetSymbolAddress((void**)&p_b3, d_b3);

    const int nnz4Blocks   = (NNZ / 4 + 255) / 256;
    const int gatherBlocks = (NTOT * 8 + 255) / 256;
    const int k1Blocks     = CONV_BLOCKS + HIST_BLOCKS + 3;

    // launch 1: fused conversion + histogram + state reset
    k1_fused<<<k1Blocks, 256>>>((const float4*)emb_user,
                                (const float4*)emb_item,
                                (const int4*)g_row);
    // launch 2: single-pass scan (d_rs, d_cur; resets d_cnt)
    k2_scan_lookback<<<NTILES, 256>>>();
    // launch 3: permute edges into CSR order
    k3_permute<<<nnz4Blocks, 256>>>((const int4*)g_row, (const int4*)g_col,
                                    (const float4*)g_val);
    // launches 4-6: propagation layers (launch 4 lands in the profiler window)
    spmm_gather_h<__half><<<gatherBlocks, 256>>>(p_h0, p_h1);
    spmm_gather_h<__half><<<gatherBlocks, 256>>>(p_h1, p_h2);
    spmm_gather_h<float ><<<gatherBlocks, 256>>>(p_h2, p_b3);
    // launch 7: fused tail
    final_kernel<<<BATCH / 32, 128>>>(emb_user, emb_item, w_user, w_item,
                                      xe1, xe0, users, items, xij, out);
}

// round 7
// speedup vs baseline: 2.3089x; 1.0018x over previous
#include <cuda_runtime.h>
#include <cuda_bf16.h>

#define N_USERS 100000
#define N_ITEMS 50000
#define NTOT    150000
#define D       64
#define NNZ     2000000
#define BATCH   16384
#define NTILES  586            // ceil(NTOT/256)
#define CONV_BLOCKS 4688       // NTOT*D/8/256
#define HIST_BLOCKS 1954       // ceil(NNZ/4/256)

// Scratch (allocation-free: __device__ globals; zero-initialized at load)
__device__ __nv_bfloat16 d_h0[NTOT * D];   // bf16 concat(emb_user, emb_item)
__device__ __nv_bfloat16 d_h1[NTOT * D];   // layer 1 output (bf16)
__device__ __nv_bfloat16 d_h2[NTOT * D];   // layer 2 output (bf16)
__device__ float   d_b3[NTOT * D];         // layer 3 output (fp32, never gathered)
__device__ int     d_cnt [NTOT];
__device__ int     d_cur [NTOT];
__device__ int     d_rs  [NTOT + 1];
__device__ unsigned long long d_tstate[NTILES];  // lookback states: flag<<32|val
__device__ float2  d_scv [NNZ];            // packed (col_as_float_bits, val)

// ---------------------------------------------------------------------------
// k1 (fused): tobf16 | histogram | lookback-state reset
// ---------------------------------------------------------------------------
__global__ void k1_fused(const float4* __restrict__ eu,
                         const float4* __restrict__ ei,
                         const int4*   __restrict__ grow4) {
    int bid = blockIdx.x;
    if (bid < CONV_BLOCKS) {
        int i = bid * 256 + threadIdx.x;            // chunk of 8 elements
        const int total8 = NTOT * D / 8;
        if (i >= total8) return;
        const int uhalf = N_USERS * D / 8;
        float4 a, b;
        if (i < uhalf) { a = eu[i * 2]; b = eu[i * 2 + 1]; }
        else { int j = i - uhalf; a = ei[j * 2]; b = ei[j * 2 + 1]; }
        __nv_bfloat162 h[4];
        h[0] = __floats2bfloat162_rn(a.x, a.y);
        h[1] = __floats2bfloat162_rn(a.z, a.w);
        h[2] = __floats2bfloat162_rn(b.x, b.y);
        h[3] = __floats2bfloat162_rn(b.z, b.w);
        ((uint4*)d_h0)[i] = *(uint4*)h;
    } else if (bid < CONV_BLOCKS + HIST_BLOCKS) {
        int i = (bid - CONV_BLOCKS) * 256 + threadIdx.x;
        if (i >= NNZ / 4) return;
        int4 r = grow4[i];
        atomicAdd(&d_cnt[r.x], 1);
        atomicAdd(&d_cnt[r.y], 1);
        atomicAdd(&d_cnt[r.z], 1);
        atomicAdd(&d_cnt[r.w], 1);
    } else {
        int i = (bid - CONV_BLOCKS - HIST_BLOCKS) * 256 + threadIdx.x;
        if (i < NTILES) d_tstate[i] = 0ULL;
    }
}

// ---------------------------------------------------------------------------
// k2: single-pass decoupled-lookback scan of d_cnt -> d_rs (exclusive).
// Also zeroes d_cnt for the next replay and initializes d_cur = d_rs.
// ---------------------------------------------------------------------------
__global__ void k2_scan_lookback() {
    __shared__ int ws[8];
    __shared__ int s_off;
    const int tile = blockIdx.x;
    const int i = tile * 256 + threadIdx.x;
    const int lane = threadIdx.x & 31, w = threadIdx.x >> 5;

    int c = (i < NTOT) ? d_cnt[i] : 0;
    if (i < NTOT) d_cnt[i] = 0;

    int x = c;
    #pragma unroll
    for (int o = 1; o < 32; o <<= 1) {
        int y = __shfl_up_sync(0xffffffffu, x, o);
        if (lane >= o) x += y;
    }
    if (lane == 31) ws[w] = x;
    __syncthreads();
    if (w == 0) {
        int s = (lane < 8) ? ws[lane] : 0;
        #pragma unroll
        for (int o = 1; o < 8; o <<= 1) {
            int y = __shfl_up_sync(0xffffffffu, s, o);
            if (lane >= o) s += y;
        }
        if (lane < 8) ws[lane] = s;
    }
    __syncthreads();
    int woff = (w > 0) ? ws[w - 1] : 0;
    int incl = x + woff;
    int total = ws[7];

    if (threadIdx.x == 0) {
        unsigned long long st = (tile == 0)
            ? ((2ULL << 32) | (unsigned)total)
            : ((1ULL << 32) | (unsigned)total);
        *(volatile unsigned long long*)&d_tstate[tile] = st;
    }

    if (w == 0) {
        int running = 0;
        int base = tile - 1;
        while (base >= 0) {
            int idx = base - lane;
            unsigned long long st;
            int flag;
            do {
                st = (idx >= 0)
                   ? *(volatile unsigned long long*)&d_tstate[idx]
                   : (2ULL << 32);
                flag = (int)(st >> 32);
            } while (__any_sync(0xffffffffu, flag == 0));
            int val = (int)(unsigned)st;
            unsigned mask = __ballot_sync(0xffffffffu, flag == 2);
            if (mask) {
                int k = __ffs(mask) - 1;
                int contrib = (lane <= k) ? val : 0;
                #pragma unroll
                for (int o = 16; o; o >>= 1)
                    contrib += __shfl_xor_sync(0xffffffffu, contrib, o);
                running += contrib;
                break;
            } else {
                int contrib = val;
                #pragma unroll
                for (int o = 16; o; o >>= 1)
                    contrib += __shfl_xor_sync(0xffffffffu, contrib, o);
                running += contrib;
                base -= 32;
            }
        }
        if (lane == 0) {
            s_off = running;
            if (tile > 0)
                *(volatile unsigned long long*)&d_tstate[tile] =
                    (2ULL << 32) | (unsigned)(running + total);
        }
    }
    __syncthreads();

    int excl = s_off + incl - c;
    if (i <= NTOT) d_rs[i] = excl;
    if (i < NTOT)  d_cur[i] = excl;
}

// ---------------------------------------------------------------------------
// k3: permute edges into CSR order (4 edges per thread, vectorized loads)
// ---------------------------------------------------------------------------
__global__ void k3_permute(const int4*   __restrict__ grow4,
                           const int4*   __restrict__ gcol4,
                           const float4* __restrict__ gval4) {
    int i = blockIdx.x * blockDim.x + threadIdx.x;
    if (i >= NNZ / 4) return;
    int4   r = grow4[i];
    int4   c = gcol4[i];
    float4 v = gval4[i];
    int p0 = atomicAdd(&d_cur[r.x], 1);
    int p1 = atomicAdd(&d_cur[r.y], 1);
    int p2 = atomicAdd(&d_cur[r.z], 1);
    int p3 = atomicAdd(&d_cur[r.w], 1);
    d_scv[p0] = make_float2(__int_as_float(c.x), v.x);
    d_scv[p1] = make_float2(__int_as_float(c.y), v.y);
    d_scv[p2] = make_float2(__int_as_float(c.z), v.z);
    d_scv[p3] = make_float2(__int_as_float(c.w), v.w);
}

// ---------------------------------------------------------------------------
// Gather SpMM over bf16 features, fp32 accumulation.
// bf16 -> fp32 unpack is pure ALU (shift / mask), no cvt instructions.
// One row per 8 lanes; each lane owns 8 bf16 (one uint4 = 16B). x4 unroll.
// ---------------------------------------------------------------------------
__device__ __forceinline__ void fma8(float* a, uint4 x, float v) {
    unsigned u[4] = {x.x, x.y, x.z, x.w};
    #pragma unroll
    for (int j = 0; j < 4; j++) {
        float lo = __uint_as_float(u[j] << 16);            // element 2j   (low half)
        float hi = __uint_as_float(u[j] & 0xffff0000u);    // element 2j+1 (high half)
        a[2 * j]     += v * lo;
        a[2 * j + 1] += v * hi;
    }
}

template <typename OUT>
__global__ void spmm_gather_h(const __nv_bfloat16* __restrict__ xin,
                              OUT*                 __restrict__ xout) {
    int gid = blockIdx.x * blockDim.x + threadIdx.x;
    int row = gid >> 3;
    int t   = gid & 7;
    if (row >= NTOT) return;
    int s = d_rs[row], e = d_rs[row + 1];
    const uint4* feat = (const uint4*)xin;      // 8 uint4 per row
    float a[8] = {0.f, 0.f, 0.f, 0.f, 0.f, 0.f, 0.f, 0.f};
    int i = s;
    for (; i + 4 <= e; i += 4) {
        float2 p0 = d_scv[i],     p1 = d_scv[i + 1];
        float2 p2 = d_scv[i + 2], p3 = d_scv[i + 3];
        uint4 x0 = feat[(size_t)__float_as_int(p0.x) * 8 + t];
        uint4 x1 = feat[(size_t)__float_as_int(p1.x) * 8 + t];
        uint4 x2 = feat[(size_t)__float_as_int(p2.x) * 8 + t];
        uint4 x3 = feat[(size_t)__float_as_int(p3.x) * 8 + t];
        fma8(a, x0, p0.y);
        fma8(a, x1, p1.y);
        fma8(a, x2, p2.y);
        fma8(a, x3, p3.y);
    }
    for (; i < e; i++) {
        float2 p = d_scv[i];
        uint4 x = feat[(size_t)__float_as_int(p.x) * 8 + t];
        fma8(a, x, p.y);
    }
    size_t base = (size_t)row * 64 + t * 8;
    if (sizeof(OUT) == 2) {                     // bf16 output (packed cvt)
        __nv_bfloat162 o[4];
        #pragma unroll
        for (int j = 0; j < 4; j++)
            o[j] = __floats2bfloat162_rn(a[2 * j], a[2 * j + 1]);
        *(uint4*)((__nv_bfloat16*)xout + base) = *(uint4*)o;
    } else {                                    // fp32 output
        float4 o0 = make_float4(a[0], a[1], a[2], a[3]);
        float4 o1 = make_float4(a[4], a[5], a[6], a[7]);
        *(float4*)((float*)xout + base)     = o0;
        *(float4*)((float*)xout + base + 4) = o1;
    }
}

// ---------------------------------------------------------------------------
// Tail: light = (emb + h1 + h2 + b3) / 4 at gathered rows, two 64x64 matvecs,
// softmax/sigmoid, dot. One warp per batch element.
// ---------------------------------------------------------------------------
__device__ __forceinline__ float bf2f(__nv_bfloat16 h) {
    return __uint_as_float(((unsigned)*(unsigned short*)&h) << 16);
}

__global__ void final_kernel(const float* __restrict__ eu,
                             const float* __restrict__ ei,
                             const float* __restrict__ w_user,
                             const float* __restrict__ w_item,
                             const float* __restrict__ xe1,
                             const float* __restrict__ xe0,
                             const int*   __restrict__ users,
                             const int*   __restrict__ items,
                             const int*   __restrict__ xij,
                             float*       __restrict__ out) {
    __shared__ float wu[64 * 65];
    __shared__ float wi[64 * 65];
    int tid = threadIdx.x;                     // 128 threads
    for (int idx = tid; idx < 64 * 64; idx += blockDim.x) {
        int r = idx >> 6, c = idx & 63;
        wu[r * 65 + c] = w_user[idx];
        wi[r * 65 + c] = w_item[idx];
    }
    __syncthreads();

    int warp = tid >> 5;
    int lane = tid & 31;

    int b_base = blockIdx.x * 32 + warp * 8;   // 512 blocks * 4 warps * 8
    for (int bi = 0; bi < 8; bi++) {
        int b = b_base + bi;
        int u  = users[b];
        int it = items[b];
        size_t uo = (size_t)u * 64;
        size_t io = (size_t)(N_USERS + it) * 64;
        size_t ie_off = (size_t)it * 64;

        float ue0 = (eu[uo + lane] + bf2f(d_h1[uo + lane]) +
                     bf2f(d_h2[uo + lane]) + d_b3[uo + lane]) * 0.25f;
        float ue1 = (eu[uo + 32 + lane] + bf2f(d_h1[uo + 32 + lane]) +
                     bf2f(d_h2[uo + 32 + lane]) + d_b3[uo + 32 + lane]) * 0.25f;
        float ie0 = (ei[ie_off + lane] + bf2f(d_h1[io + lane]) +
                     bf2f(d_h2[io + lane]) + d_b3[io + lane]) * 0.25f;
        float ie1 = (ei[ie_off + 32 + lane] + bf2f(d_h1[io + 32 + lane]) +
                     bf2f(d_h2[io + 32 + lane]) + d_b3[io + 32 + lane]) * 0.25f;

        float po0 = 0.f, po1 = 0.f, qo0 = 0.f, qo1 = 0.f;
        #pragma unroll
        for (int k = 0; k < 32; k++) {
            float au = __shfl_sync(0xffffffffu, ue0, k);
            float ai = __shfl_sync(0xffffffffu, ie0, k);
            po0 += au * wu[lane * 65 + k];
            po1 += au * wu[(lane + 32) * 65 + k];
            qo0 += ai * wi[lane * 65 + k];
            qo1 += ai * wi[(lane + 32) * 65 + k];
        }
        #pragma unroll
        for (int k = 0; k < 32; k++) {
            float au = __shfl_sync(0xffffffffu, ue1, k);
            float ai = __shfl_sync(0xffffffffu, ie1, k);
            po0 += au * wu[lane * 65 + 32 + k];
            po1 += au * wu[(lane + 32) * 65 + 32 + k];
            qo0 += ai * wi[lane * 65 + 32 + k];
            qo1 += ai * wi[(lane + 32) * 65 + 32 + k];
        }

        float m = fmaxf(po0, po1);
        #pragma unroll
        for (int o = 16; o; o >>= 1)
            m = fmaxf(m, __shfl_xor_sync(0xffffffffu, m, o));
        float e0 = expf(po0 - m);
        float e1 = expf(po1 - m);
        float s = e0 + e1;
        #pragma unroll
        for (int o = 16; o; o >>= 1)
            s += __shfl_xor_sync(0xffffffffu, s, o);
        float scale = 0.5f / s;                 // (1 - hx) * softmax

        float sg0 = 1.f / (1.f + expf(-qo0));
        float sg1 = 1.f / (1.f + expf(-qo1));

        float part = scale * (e0 * sg0 + e1 * sg1);
        #pragma unroll
        for (int o = 16; o; o >>= 1)
            part += __shfl_xor_sync(0xffffffffu, part, o);

        if (lane == 0) {
            float xe  = (xij[b] > 0) ? xe1[it] : xe0[it];
            float sgx = 1.f / (1.f + expf(-xe));
            out[b] = part + 0.5f * sgx;
        }
    }
}

// ---------------------------------------------------------------------------
extern "C" void kernel_launch(void* const* d_in, const int* in_sizes, int n_in,
                              void* d_out, int out_size) {
    (void)in_sizes; (void)n_in; (void)out_size;
    const float* emb_user = (const float*)d_in[0];
    const float* emb_item = (const float*)d_in[1];
    const float* w_user   = (const float*)d_in[2];
    const float* w_item   = (const float*)d_in[3];
    const float* xe1      = (const float*)d_in[4];
    const float* xe0      = (const float*)d_in[5];
    const float* g_val    = (const float*)d_in[6];
    const int*   g_row    = (const int*)d_in[7];
    const int*   g_col    = (const int*)d_in[8];
    const int*   users    = (const int*)d_in[9];
    const int*   items    = (const int*)d_in[10];
    const int*   xij      = (const int*)d_in[11];
    float* out = (float*)d_out;

    __nv_bfloat16 *p_h0, *p_h1, *p_h2;
    float *p_b3;
    cudaGetSymbolAddress((void**)&p_h0, d_h0);
    cudaGetSymbolAddress((void**)&p_h1, d_h1);
    cudaGetSymbolAddress((void**)&p_h2, d_h2);
    cudaGetSymbolAddress((void**)&p_b3, d_b3);

    const int nnz4Blocks   = (NNZ / 4 + 255) / 256;
    const int gatherBlocks = (NTOT * 8 + 255) / 256;
    const int k1Blocks     = CONV_BLOCKS + HIST_BLOCKS + 3;

    k1_fused<<<k1Blocks, 256>>>((const float4*)emb_user,
                                (const float4*)emb_item,
                                (const int4*)g_row);
    k2_scan_lookback<<<NTILES, 256>>>();
    k3_permute<<<nnz4Blocks, 256>>>((const int4*)g_row, (const int4*)g_col,
                                    (const float4*)g_val);
    spmm_gather_h<__nv_bfloat16><<<gatherBlocks, 256>>>(p_h0, p_h1);
    spmm_gather_h<__nv_bfloat16><<<gatherBlocks, 256>>>(p_h1, p_h2);
    spmm_gather_h<float        ><<<gatherBlocks, 256>>>(p_h2, p_b3);
    final_kernel<<<BATCH / 32, 128>>>(emb_user, emb_item, w_user, w_item,
                                      xe1, xe0, users, items, xij, out);
}